// round 4
// baseline (speedup 1.0000x reference)
#include <cuda_runtime.h>
#include <cuda_bf16.h>

#define NN 100000
#define EE 1600000
#define TOT_EDGES (EE + NN)   // edges + self loops

// ---------------- scratch (no allocation allowed) ----------------
__device__ float g_h1[NN * 128];
__device__ float g_h2[NN * 128];
__device__ float g_xcomb[NN * 256];
__device__ float g_as1[NN * 2];
__device__ float g_ad1[NN * 2];
__device__ float g_as2[NN * 2];
__device__ float g_ad2[NN * 2];
__device__ int   g_cnt[NN];
__device__ int   g_offs[NN + 1];
__device__ int   g_cur[NN];
__device__ int   g_csr[TOT_EDGES];

// ---------------- f32x2 packed helpers (sm_100+) ----------------
__device__ __forceinline__ unsigned long long pack2(float x) {
    unsigned long long r;
    asm("mov.b64 %0, {%1, %1};" : "=l"(r) : "f"(x));
    return r;
}
__device__ __forceinline__ void ffma2(unsigned long long& d,
                                      unsigned long long a,
                                      unsigned long long b) {
    asm("fma.rn.f32x2 %0, %1, %2, %0;" : "+l"(d) : "l"(a), "l"(b));
}
__device__ __forceinline__ float2 unpack2(unsigned long long u) {
    float2 f;
    asm("mov.b64 {%0, %1}, %2;" : "=f"(f.x), "=f"(f.y) : "l"(u));
    return f;
}

// ---------------- GEMM: C[M,Nf] = A[M,K] @ B[K,Nf] (+bias) ----------------
// BM=128, BN=64, BK=32, 256 threads, per-thread 8x4 via f32x2 pairs along M.
// As stored transposed [k][m] with an 8-float-block XOR swizzle to keep both
// the STS (A-tile fill) and the LDS (ulonglong2 a-frag) near conflict-free.
#define ASWZ(k, m) ((k)*128 + (((((m) >> 3) ^ (((k) >> 2) & 3))) << 3) + ((m) & 7))

__global__ __launch_bounds__(256, 2) void gemm_kernel(
    const float* __restrict__ A, const float* __restrict__ B,
    const float* __restrict__ bias, float* __restrict__ C,
    int M, int Nf, int K)
{
    __shared__ float As_f[32 * 128];
    __shared__ float Bs[32][64];

    const int tid = threadIdx.x;
    const int tx = tid & 15;          // N direction (4 cols)
    const int ty = tid >> 4;          // M direction (8 rows)
    const int m0 = blockIdx.x * 128;
    const int n0 = blockIdx.y * 64;

    unsigned long long acc[4][4];
#pragma unroll
    for (int i = 0; i < 4; i++)
#pragma unroll
        for (int j = 0; j < 4; j++) acc[i][j] = 0ull;

    for (int k0 = 0; k0 < K; k0 += 32) {
        // A tile: 128 rows x 32 k  (1024 float4, 4 per thread), coalesced along k
#pragma unroll
        for (int i = 0; i < 4; i++) {
            int p = i * 256 + tid;
            int row = p >> 3;
            int c4 = p & 7;
            int gm = m0 + row;
            float4 v = make_float4(0.f, 0.f, 0.f, 0.f);
            if (gm < M) v = *(const float4*)&A[(size_t)gm * K + k0 + c4 * 4];
            int kk = c4 * 4;
            As_f[ASWZ(kk + 0, row)] = v.x;
            As_f[ASWZ(kk + 1, row)] = v.y;
            As_f[ASWZ(kk + 2, row)] = v.z;
            As_f[ASWZ(kk + 3, row)] = v.w;
        }
        // B tile: 32 k x 64 n (512 float4, 2 per thread)
#pragma unroll
        for (int i = 0; i < 2; i++) {
            int p = i * 256 + tid;
            int row = p >> 4;
            int c4 = p & 15;
            float4 v = *(const float4*)&B[(size_t)(k0 + row) * Nf + n0 + c4 * 4];
            *(float4*)&Bs[row][c4 * 4] = v;
        }
        __syncthreads();

#pragma unroll
        for (int k = 0; k < 32; k++) {
            int abase = k * 128 + (((ty ^ ((k >> 2) & 3)) << 3));
            ulonglong2 a01 = *(const ulonglong2*)&As_f[abase];
            ulonglong2 a23 = *(const ulonglong2*)&As_f[abase + 4];
            float4 bv = *(const float4*)&Bs[k][tx * 4];
            unsigned long long b0 = pack2(bv.x);
            unsigned long long b1 = pack2(bv.y);
            unsigned long long b2 = pack2(bv.z);
            unsigned long long b3 = pack2(bv.w);
            ffma2(acc[0][0], a01.x, b0); ffma2(acc[0][1], a01.x, b1);
            ffma2(acc[0][2], a01.x, b2); ffma2(acc[0][3], a01.x, b3);
            ffma2(acc[1][0], a01.y, b0); ffma2(acc[1][1], a01.y, b1);
            ffma2(acc[1][2], a01.y, b2); ffma2(acc[1][3], a01.y, b3);
            ffma2(acc[2][0], a23.x, b0); ffma2(acc[2][1], a23.x, b1);
            ffma2(acc[2][2], a23.x, b2); ffma2(acc[2][3], a23.x, b3);
            ffma2(acc[3][0], a23.y, b0); ffma2(acc[3][1], a23.y, b1);
            ffma2(acc[3][2], a23.y, b2); ffma2(acc[3][3], a23.y, b3);
        }
        __syncthreads();
    }

    float4 bvv = make_float4(0.f, 0.f, 0.f, 0.f);
    if (bias) bvv = *(const float4*)&bias[n0 + tx * 4];

#pragma unroll
    for (int i = 0; i < 4; i++) {
        float2 v0 = unpack2(acc[i][0]);
        float2 v1 = unpack2(acc[i][1]);
        float2 v2 = unpack2(acc[i][2]);
        float2 v3 = unpack2(acc[i][3]);
        int r0 = m0 + ty * 8 + 2 * i;
        if (r0 < M) {
            float4 o = make_float4(v0.x + bvv.x, v1.x + bvv.y, v2.x + bvv.z, v3.x + bvv.w);
            *(float4*)&C[(size_t)r0 * Nf + n0 + tx * 4] = o;
        }
        if (r0 + 1 < M) {
            float4 o = make_float4(v0.y + bvv.x, v1.y + bvv.y, v2.y + bvv.z, v3.y + bvv.w);
            *(float4*)&C[(size_t)(r0 + 1) * Nf + n0 + tx * 4] = o;
        }
    }
}

// ---------------- attention coefficients ----------------
// one warp per node; handles both layers. a_src[n,h] = sum_c h[n,h,c]*att_src[h,c]
__global__ __launch_bounds__(256) void acoef_kernel(
    const float* __restrict__ h1, const float* __restrict__ h2,
    const float* __restrict__ as1, const float* __restrict__ ad1,
    const float* __restrict__ as2, const float* __restrict__ ad2,
    float* __restrict__ oas1, float* __restrict__ oad1,
    float* __restrict__ oas2, float* __restrict__ oad2)
{
    int node = (blockIdx.x * blockDim.x + threadIdx.x) >> 5;
    if (node >= NN) return;
    int lane = threadIdx.x & 31;
    int hl = lane >> 4;

#pragma unroll
    for (int L = 0; L < 2; L++) {
        const float* h = (L == 0) ? h1 : h2;
        const float* ats = (L == 0) ? as1 : as2;
        const float* atd = (L == 0) ? ad1 : ad2;
        float* oas = (L == 0) ? oas1 : oas2;
        float* oad = (L == 0) ? oad1 : oad2;

        float4 hv = *(const float4*)&h[(size_t)node * 128 + lane * 4];
        float4 sv = *(const float4*)&ats[lane * 4];
        float4 dv = *(const float4*)&atd[lane * 4];
        float ps = hv.x * sv.x + hv.y * sv.y + hv.z * sv.z + hv.w * sv.w;
        float pd = hv.x * dv.x + hv.y * dv.y + hv.z * dv.z + hv.w * dv.w;
#pragma unroll
        for (int o = 8; o > 0; o >>= 1) {
            ps += __shfl_xor_sync(0xffffffffu, ps, o);
            pd += __shfl_xor_sync(0xffffffffu, pd, o);
        }
        if ((lane & 15) == 0) {
            oas[node * 2 + hl] = ps;
            oad[node * 2 + hl] = pd;
        }
    }
}

// ---------------- CSR build ----------------
__global__ void init_cnt_kernel(int* __restrict__ cnt) {
    int i = blockIdx.x * blockDim.x + threadIdx.x;
    if (i < NN) cnt[i] = 1;  // self loop
}

__global__ void count_edges_kernel(const int* __restrict__ ei, int* __restrict__ cnt) {
    int j = blockIdx.x * blockDim.x + threadIdx.x;
    if (j < EE) atomicAdd(&cnt[ei[EE + j]], 1);
}

// single-block exclusive scan of cnt[NN] -> offs[NN+1], also copies into cur
__global__ __launch_bounds__(1024) void scan_kernel(
    const int* __restrict__ cnt, int* __restrict__ offs, int* __restrict__ cur)
{
    __shared__ int sums[1024];
    const int CH = (NN + 1023) / 1024;  // 98
    int t = threadIdx.x;
    int base = t * CH;
    int local = 0;
    for (int i = 0; i < CH; i++) {
        int idx = base + i;
        if (idx < NN) local += cnt[idx];
    }
    sums[t] = local;
    __syncthreads();
#pragma unroll
    for (int off = 1; off < 1024; off <<= 1) {
        int v = (t >= off) ? sums[t - off] : 0;
        __syncthreads();
        sums[t] += v;
        __syncthreads();
    }
    int run = sums[t] - local;  // exclusive prefix
    for (int i = 0; i < CH; i++) {
        int idx = base + i;
        if (idx < NN) {
            offs[idx] = run;
            cur[idx] = run;
            run += cnt[idx];
        }
    }
    if (base < NN && base + CH >= NN) offs[NN] = run;
}

__global__ void fill_edges_kernel(const int* __restrict__ ei,
                                  int* __restrict__ cur, int* __restrict__ csr) {
    int j = blockIdx.x * blockDim.x + threadIdx.x;
    if (j >= TOT_EDGES) return;
    int s, d;
    if (j < EE) { s = ei[j]; d = ei[EE + j]; }
    else        { s = d = j - EE; }
    int pos = atomicAdd(&cur[d], 1);
    csr[pos] = s;
}

// ---------------- aggregation: one warp per dst node ----------------
// lanes 0-15 -> head 0, lanes 16-31 -> head 1; each lane owns 4 channels.
// two-pass softmax (local max, then exp/sum + weighted gather of h[src]).
__global__ __launch_bounds__(256) void agg_kernel(
    const float* __restrict__ h, const float* __restrict__ asrc,
    const float* __restrict__ adst, const int* __restrict__ offs,
    const int* __restrict__ csr, const float* __restrict__ bias,
    float* __restrict__ xcomb, int colOff)
{
    int node = (blockIdx.x * blockDim.x + threadIdx.x) >> 5;
    if (node >= NN) return;
    int lane = threadIdx.x & 31;
    int hl = lane >> 4;
    int c4 = (lane & 15) * 4;

    float ad = adst[node * 2 + hl];
    int beg = offs[node];
    int end = offs[node + 1];

    float mx = -1e30f;
    for (int j = beg; j < end; ++j) {
        int s = csr[j];
        float e = asrc[s * 2 + hl] + ad;
        e = (e > 0.f) ? e : 0.2f * e;
        mx = fmaxf(mx, e);
    }

    float sum = 0.f;
    float4 acc = make_float4(0.f, 0.f, 0.f, 0.f);
    for (int j = beg; j < end; ++j) {
        int s = csr[j];
        float e = asrc[s * 2 + hl] + ad;
        e = (e > 0.f) ? e : 0.2f * e;
        float p = __expf(e - mx);
        sum += p;
        float4 hv = *(const float4*)&h[(size_t)s * 128 + hl * 64 + c4];
        acc.x = fmaf(hv.x, p, acc.x);
        acc.y = fmaf(hv.y, p, acc.y);
        acc.z = fmaf(hv.z, p, acc.z);
        acc.w = fmaf(hv.w, p, acc.w);
    }

    float inv = 1.f / sum;
    float4 bv = *(const float4*)&bias[hl * 64 + c4];
    float4 r;
    r.x = fmaxf(fmaf(acc.x, inv, bv.x), 0.f);
    r.y = fmaxf(fmaf(acc.y, inv, bv.y), 0.f);
    r.z = fmaxf(fmaf(acc.z, inv, bv.z), 0.f);
    r.w = fmaxf(fmaf(acc.w, inv, bv.w), 0.f);
    *(float4*)&xcomb[(size_t)node * 256 + colOff + hl * 64 + c4] = r;
}

// ---------------- launch ----------------
extern "C" void kernel_launch(void* const* d_in, const int* in_sizes, int n_in,
                              void* d_out, int out_size) {
    const float* x    = (const float*)d_in[0];
    const int*   eic  = (const int*)d_in[1];
    const int*   eil  = (const int*)d_in[2];
    const float* W1   = (const float*)d_in[3];
    const float* as1  = (const float*)d_in[4];
    const float* ad1  = (const float*)d_in[5];
    const float* b1   = (const float*)d_in[6];
    const float* W2   = (const float*)d_in[7];
    const float* as2  = (const float*)d_in[8];
    const float* ad2  = (const float*)d_in[9];
    const float* b2   = (const float*)d_in[10];
    const float* fcW  = (const float*)d_in[11];
    const float* fcb  = (const float*)d_in[12];
    float* out = (float*)d_out;

    float *h1, *h2, *xcomb, *pas1, *pad1, *pas2, *pad2;
    int *cnt, *offs, *cur, *csr;
    cudaGetSymbolAddress((void**)&h1, g_h1);
    cudaGetSymbolAddress((void**)&h2, g_h2);
    cudaGetSymbolAddress((void**)&xcomb, g_xcomb);
    cudaGetSymbolAddress((void**)&pas1, g_as1);
    cudaGetSymbolAddress((void**)&pad1, g_ad1);
    cudaGetSymbolAddress((void**)&pas2, g_as2);
    cudaGetSymbolAddress((void**)&pad2, g_ad2);
    cudaGetSymbolAddress((void**)&cnt, g_cnt);
    cudaGetSymbolAddress((void**)&offs, g_offs);
    cudaGetSymbolAddress((void**)&cur, g_cur);
    cudaGetSymbolAddress((void**)&csr, g_csr);

    const int M = NN, K = 256;
    dim3 gH((M + 127) / 128, 2);   // Nf = 128
    dim3 gF((M + 127) / 128, 1);   // Nf = 64

    // feature transforms
    gemm_kernel<<<gH, 256>>>(x, W1, nullptr, h1, M, 128, K);
    gemm_kernel<<<gH, 256>>>(x, W2, nullptr, h2, M, 128, K);
    acoef_kernel<<<(NN * 32 + 255) / 256, 256>>>(h1, h2, as1, ad1, as2, ad2,
                                                 pas1, pad1, pas2, pad2);

    const int cntBlocks  = (NN + 255) / 256;
    const int edgeBlocks = (EE + 255) / 256;
    const int fillBlocks = (TOT_EDGES + 255) / 256;
    const int aggBlocks  = (NN * 32 + 255) / 256;

    // layer 1 (connected)
    init_cnt_kernel<<<cntBlocks, 256>>>(cnt);
    count_edges_kernel<<<edgeBlocks, 256>>>(eic, cnt);
    scan_kernel<<<1, 1024>>>(cnt, offs, cur);
    fill_edges_kernel<<<fillBlocks, 256>>>(eic, cur, csr);
    agg_kernel<<<aggBlocks, 256>>>(h1, pas1, pad1, offs, csr, b1, xcomb, 0);

    // layer 2 (liked)
    init_cnt_kernel<<<cntBlocks, 256>>>(cnt);
    count_edges_kernel<<<edgeBlocks, 256>>>(eil, cnt);
    scan_kernel<<<1, 1024>>>(cnt, offs, cur);
    fill_edges_kernel<<<fillBlocks, 256>>>(eil, cur, csr);
    agg_kernel<<<aggBlocks, 256>>>(h2, pas2, pad2, offs, csr, b2, xcomb, 128);

    // final FC
    gemm_kernel<<<gF, 256>>>(xcomb, fcW, fcb, out, M, 64, K);
}